// round 13
// baseline (speedup 1.0000x reference)
#include <cuda_runtime.h>
#include <cstdint>
#include <cmath>

#define HID   640
#define ADIM  128
#define WPB   148     // warp-partials per batch -> 2368 warps = 296 blocks = 2/SM
#define MAXB  16
#define DEPTH 4       // cp.async pipeline depth (rows in flight per warp)
#define ROWB  2560    // bytes per row (HID * 4)

// ---- device scratch (no allocations allowed) ----
__device__ float g_q[MAXB * ADIM];
__device__ float g_r[MAXB * HID];
__device__ float g_pacc[(size_t)MAXB * WPB * HID];  // 6 MB
__device__ float g_pm[MAXB * WPB];
__device__ float g_ps[MAXB * WPB];
__device__ float g_pooled[MAXB * HID];
__device__ float g_y[MAXB * HID];

__device__ __forceinline__ void cp16(unsigned int s, const void* g) {
    asm volatile("cp.async.cg.shared.global [%0], [%1], 16;" :: "r"(s), "l"(g));
}
__device__ __forceinline__ void cp_commit() {
    asm volatile("cp.async.commit_group;");
}
template <int N>
__device__ __forceinline__ void cp_wait() {
    asm volatile("cp.async.wait_group %0;" :: "n"(N));
}

// ---------------------------------------------------------------------------
// Kernel 1a: q[b,a] = dot(Wq[a,:], pos[b,:])   — one warp per output
// ---------------------------------------------------------------------------
__global__ void __launch_bounds__(256) k_q(const float* __restrict__ pos,
                                           const float* __restrict__ Wq) {
    int gw   = blockIdx.x * 8 + (threadIdx.x >> 5);
    int lane = threadIdx.x & 31;
    int b = gw >> 7;
    int a = gw & 127;

    const float* wr = Wq + (size_t)a * HID;
    const float* pr = pos + (size_t)b * HID;
    float s = 0.f;
    #pragma unroll
    for (int k = 0; k < HID / 32; k++) {
        int h = lane + 32 * k;
        s += wr[h] * pr[h];
    }
    #pragma unroll
    for (int o = 16; o > 0; o >>= 1) s += __shfl_xor_sync(0xffffffffu, s, o);
    if (lane == 0) g_q[b * ADIM + a] = s;
}

// ---------------------------------------------------------------------------
// Kernel 1b: r[b,h] = scale * sum_a Wk[a,h] * q[b,a]
// grid (B,5) x 512: 128 h per block, 4 threads per h (32 a's each)
// ---------------------------------------------------------------------------
__global__ void __launch_bounds__(512) k_r(const float* __restrict__ Wk,
                                           float scale) {
    int b = blockIdx.x;
    int t = threadIdx.x;
    int h = blockIdx.y * 128 + (t & 127);
    int q = t >> 7;

    __shared__ float qs[ADIM];
    if (t < ADIM) qs[t] = g_q[b * ADIM + t];
    __syncthreads();

    float s = 0.f;
    int a0 = q * 32;
    #pragma unroll
    for (int a = 0; a < 32; a++)
        s += Wk[(size_t)(a0 + a) * HID + h] * qs[a0 + a];

    __shared__ float red[512];
    red[t] = s;
    __syncthreads();
    if (q == 0)
        g_r[b * HID + h] = (s + red[t + 128] + red[t + 256] + red[t + 384]) * scale;
}

// ---------------------------------------------------------------------------
// Kernel 2: streaming pass over gene_hiddens (819 MB) via cp.async pipeline.
// Warp-private 4-deep row pipeline in dynamic SMEM: loads live in SMEM, not
// registers, so in-flight bytes/SM (120KB) >> latency-BW product (~26KB).
// Each lane copies + reads back its own 80B of the row (no cross-lane sync).
// ---------------------------------------------------------------------------
extern __shared__ char s_pipe[];

__global__ void __launch_bounds__(256) k_pass1(const float* __restrict__ gh,
                                               int B, int N) {
    int warp = threadIdx.x >> 5;
    int lane = threadIdx.x & 31;
    int wg   = blockIdx.x * 8 + warp;
    int b    = wg / WPB;
    int w    = wg % WPB;
    if (b >= B) return;

    int rpw = (N + WPB - 1) / WPB;        // 136
    int n0  = w * rpw;
    int n1  = min(N, n0 + rpw);

    // warp-private smem region: DEPTH row buffers
    char* wbase = s_pipe + (size_t)warp * DEPTH * ROWB;
    unsigned int wbase_s = (unsigned int)__cvta_generic_to_shared(wbase) + lane * 16;
    const char* gbase = (const char*)(gh + (size_t)b * N * HID);

    const float4* rb = reinterpret_cast<const float4*>(g_r + b * HID);
    float4 rr[5], acc[5];
    #pragma unroll
    for (int k = 0; k < 5; k++) {
        rr[k]  = rb[lane + 32 * k];
        acc[k] = make_float4(0.f, 0.f, 0.f, 0.f);
    }

    // ---- prologue: issue DEPTH-1 rows (clamped at n1-1) ----
    #pragma unroll
    for (int j = 0; j < DEPTH - 1; j++) {
        int n = min(n0 + j, n1 - 1);
        const char* src = gbase + (size_t)n * ROWB + lane * 16;
        unsigned int dst = wbase_s + j * ROWB;
        #pragma unroll
        for (int k = 0; k < 5; k++) cp16(dst + k * 512, src + k * 512);
        cp_commit();
    }

    float m = -1e30f, s = 0.f;

    for (int i = n0; i < n1; i++) {
        cp_wait<DEPTH - 2>();             // row i complete (self-copied data)

        int slot = (i - n0) % DEPTH;
        const float4* srow = reinterpret_cast<const float4*>(wbase + slot * ROWB);
        float4 hv[5];
        #pragma unroll
        for (int k = 0; k < 5; k++) hv[k] = srow[lane + 32 * k];

        // refill: issue row i+DEPTH-1 (clamped) into the slot just freed
        {
            int nn  = min(i + DEPTH - 1, n1 - 1);
            int isl = (i - n0 + DEPTH - 1) % DEPTH;
            const char* src = gbase + (size_t)nn * ROWB + lane * 16;
            unsigned int dst = wbase_s + isl * ROWB;
            #pragma unroll
            for (int k = 0; k < 5; k++) cp16(dst + k * 512, src + k * 512);
            cp_commit();
        }

        float d = 0.f;
        #pragma unroll
        for (int k = 0; k < 5; k++)
            d += hv[k].x * rr[k].x + hv[k].y * rr[k].y
               + hv[k].z * rr[k].z + hv[k].w * rr[k].w;
        #pragma unroll
        for (int o = 16; o > 0; o >>= 1) d += __shfl_xor_sync(0xffffffffu, d, o);

        if (d > m) {
            float c = __expf(m - d);
            s *= c;
            #pragma unroll
            for (int k = 0; k < 5; k++) {
                acc[k].x *= c; acc[k].y *= c; acc[k].z *= c; acc[k].w *= c;
            }
            m = d;
        }
        float wt = __expf(d - m);
        s += wt;
        #pragma unroll
        for (int k = 0; k < 5; k++) {
            acc[k].x += wt * hv[k].x; acc[k].y += wt * hv[k].y;
            acc[k].z += wt * hv[k].z; acc[k].w += wt * hv[k].w;
        }
    }
    cp_wait<0>();                         // drain before exit

    float4* pa = reinterpret_cast<float4*>(g_pacc + (size_t)(b * WPB + w) * HID);
    #pragma unroll
    for (int k = 0; k < 5; k++) pa[lane + 32 * k] = acc[k];
    if (lane == 0) { g_pm[b * WPB + w] = m; g_ps[b * WPB + w] = s; }
}

// ---------------------------------------------------------------------------
// Kernel 3: pooled[b,h] = invS * sum_i wsm[i] * pacc[b,i,h]
// grid (B, 10) x 256: 64 h per block, 4 threads per h (37 partials each).
// ---------------------------------------------------------------------------
__global__ void __launch_bounds__(256) k_pooled(int dummy) {
    int b = blockIdx.x;
    int t = threadIdx.x;
    int lane = t & 31, wid = t >> 5;

    __shared__ float wsm[WPB];
    __shared__ float sred[8];
    __shared__ float sInvS;

    float pm = (t < WPB) ? g_pm[b * WPB + t] : -1e30f;
    float ps = (t < WPB) ? g_ps[b * WPB + t] : 0.f;

    float mv = pm;
    #pragma unroll
    for (int o = 16; o > 0; o >>= 1)
        mv = fmaxf(mv, __shfl_xor_sync(0xffffffffu, mv, o));
    if (lane == 0) sred[wid] = mv;
    __syncthreads();
    float M = sred[0];
    #pragma unroll
    for (int i = 1; i < 8; i++) M = fmaxf(M, sred[i]);
    __syncthreads();

    float w = (t < WPB) ? __expf(pm - M) : 0.f;
    if (t < WPB) wsm[t] = w;
    float sv = w * ps;
    #pragma unroll
    for (int o = 16; o > 0; o >>= 1) sv += __shfl_xor_sync(0xffffffffu, sv, o);
    if (lane == 0) sred[wid] = sv;
    __syncthreads();
    if (t == 0) {
        float S = 0.f;
        #pragma unroll
        for (int i = 0; i < 8; i++) S += sred[i];
        sInvS = 1.f / S;
    }
    __syncthreads();

    // 4 threads per h, 37 partials each
    int h = blockIdx.y * 64 + (t & 63);
    int q = t >> 6;
    const float* pa = g_pacc + (size_t)b * WPB * HID + h;

    float a = 0.f;
    int i0 = q * 37;
    #pragma unroll
    for (int i = i0; i < i0 + 37; i++)
        a += wsm[i] * pa[(size_t)i * HID];

    __shared__ float red[256];
    red[t] = a;
    __syncthreads();
    if (q == 0)
        g_pooled[b * HID + h] =
            (a + red[t + 64] + red[t + 128] + red[t + 192]) * sInvS;
}

// ---------------------------------------------------------------------------
// Kernel 4: y[b,v] = dot(Wv[v,:], pooled[b,:])
// ---------------------------------------------------------------------------
__global__ void __launch_bounds__(256) k_y(const float* __restrict__ Wv) {
    int gw   = blockIdx.x * 8 + (threadIdx.x >> 5);
    int lane = threadIdx.x & 31;
    int v = gw >> 4;
    int b = gw & 15;

    const float* wr = Wv + (size_t)v * HID;
    const float* pr = g_pooled + (size_t)b * HID;
    float s = 0.f;
    #pragma unroll
    for (int k = 0; k < HID / 32; k++) {
        int h = lane + 32 * k;
        s += wr[h] * pr[h];
    }
    #pragma unroll
    for (int o = 16; o > 0; o >>= 1) s += __shfl_xor_sync(0xffffffffu, s, o);
    if (lane == 0) g_y[b * HID + v] = s;
}

// ---------------------------------------------------------------------------
// Kernel 5: LayerNorm over 640. grid=B, block=640.
// ---------------------------------------------------------------------------
__device__ __forceinline__ float block_sum_640(float v, float* sred, int t) {
    int lane = t & 31, wid = t >> 5;
    #pragma unroll
    for (int o = 16; o > 0; o >>= 1) v += __shfl_xor_sync(0xffffffffu, v, o);
    if (lane == 0) sred[wid] = v;
    __syncthreads();
    if (wid == 0) {
        float x = (lane < 20) ? sred[lane] : 0.f;
        #pragma unroll
        for (int o = 16; o > 0; o >>= 1) x += __shfl_xor_sync(0xffffffffu, x, o);
        if (lane == 0) sred[0] = x;
    }
    __syncthreads();
    float r = sred[0];
    __syncthreads();
    return r;
}

__global__ void __launch_bounds__(640) k_ln(const float* __restrict__ gamma,
                                            const float* __restrict__ beta,
                                            float* __restrict__ out) {
    int b = blockIdx.x;
    int t = threadIdx.x;
    __shared__ float sred[32];

    float x = g_y[b * HID + t];
    float mean = block_sum_640(x, sred, t) * (1.f / HID);
    float dx = x - mean;
    float var = block_sum_640(dx * dx, sred, t) * (1.f / HID);
    out[b * HID + t] = dx * rsqrtf(var + 1e-5f) * gamma[t] + beta[t];
}

// ---------------------------------------------------------------------------
extern "C" void kernel_launch(void* const* d_in, const int* in_sizes, int n_in,
                              void* d_out, int out_size) {
    const float* gh    = (const float*)d_in[0];
    const float* pos   = (const float*)d_in[1];
    const float* Wq    = (const float*)d_in[2];
    const float* Wk    = (const float*)d_in[3];
    const float* Wv    = (const float*)d_in[4];
    const float* gamma = (const float*)d_in[5];
    const float* beta  = (const float*)d_in[6];
    float* out = (float*)d_out;

    int B = in_sizes[1] / HID;             // 16
    int N = in_sizes[0] / (B * HID);       // 20000
    float scale = 1.0f / sqrtf((float)ADIM);

    k_q<<<(B * ADIM) / 8, 256>>>(pos, Wq);            // 256 blocks
    k_r<<<dim3(B, 5), 512>>>(Wk, scale);              // 80 blocks

    const int smem = 8 * DEPTH * ROWB;                 // 81920 B
    static bool attr_set = false;
    if (!attr_set) {
        cudaFuncSetAttribute(k_pass1, cudaFuncAttributeMaxDynamicSharedMemorySize, smem);
        attr_set = true;
    }
    int blocks = (B * WPB) / 8;            // 296 blocks = 2/SM (smem-limited)
    k_pass1<<<blocks, 256, smem>>>(gh, B, N);

    k_pooled<<<dim3(B, 10), 256>>>(0);                // 160 blocks
    k_y<<<(B * HID) / 8, 256>>>(Wv);                  // 1280 blocks
    k_ln<<<B, HID>>>(gamma, beta, out);
}

// round 14
// speedup vs baseline: 1.0367x; 1.0367x over previous
#include <cuda_runtime.h>
#include <cstdint>
#include <cmath>

#define HID  640
#define ADIM 128
#define WPB  148     // warp-partials per batch -> 2368 warps = 296 blocks = 2/SM
#define MAXB 16

// ---- device scratch (no allocations allowed) ----
__device__ float g_q[MAXB * ADIM];
__device__ float g_r[MAXB * HID];
__device__ float g_pacc[(size_t)MAXB * WPB * HID];  // 6 MB
__device__ float g_pm[MAXB * WPB];
__device__ float g_ps[MAXB * WPB];
__device__ float g_pooled[MAXB * HID];
__device__ float g_y[MAXB * HID];

// ---------------------------------------------------------------------------
// Kernel 1a: q[b,a] = dot(Wq[a,:], pos[b,:])   — one warp per output
// ---------------------------------------------------------------------------
__global__ void __launch_bounds__(256) k_q(const float* __restrict__ pos,
                                           const float* __restrict__ Wq) {
    int gw   = blockIdx.x * 8 + (threadIdx.x >> 5);
    int lane = threadIdx.x & 31;
    int b = gw >> 7;
    int a = gw & 127;

    const float* wr = Wq + (size_t)a * HID;
    const float* pr = pos + (size_t)b * HID;
    float s = 0.f;
    #pragma unroll
    for (int k = 0; k < HID / 32; k++) {
        int h = lane + 32 * k;
        s += wr[h] * pr[h];
    }
    #pragma unroll
    for (int o = 16; o > 0; o >>= 1) s += __shfl_xor_sync(0xffffffffu, s, o);
    if (lane == 0) g_q[b * ADIM + a] = s;
}

// ---------------------------------------------------------------------------
// Kernel 1b: r[b,h] = scale * sum_a Wk[a,h] * q[b,a]
// grid (B,5) x 512: 128 h per block, 4 threads per h (32 a's each)
// ---------------------------------------------------------------------------
__global__ void __launch_bounds__(512) k_r(const float* __restrict__ Wk,
                                           float scale) {
    int b = blockIdx.x;
    int t = threadIdx.x;
    int h = blockIdx.y * 128 + (t & 127);
    int q = t >> 7;

    __shared__ float qs[ADIM];
    if (t < ADIM) qs[t] = g_q[b * ADIM + t];
    __syncthreads();

    float s = 0.f;
    int a0 = q * 32;
    #pragma unroll
    for (int a = 0; a < 32; a++)
        s += Wk[(size_t)(a0 + a) * HID + h] * qs[a0 + a];

    __shared__ float red[512];
    red[t] = s;
    __syncthreads();
    if (q == 0)
        g_r[b * HID + h] = (s + red[t + 128] + red[t + 256] + red[t + 384]) * scale;
}

// ---------------------------------------------------------------------------
// Kernel 2: streaming pass over gene_hiddens (819 MB), 2-ROW LDG pipeline
// (R8/R11-proven: ~118us, the measured ceiling for this pattern).
// ---------------------------------------------------------------------------
__global__ void __launch_bounds__(256, 2) k_pass1(const float* __restrict__ gh,
                                                  int B, int N) {
    int wg   = blockIdx.x * 8 + (threadIdx.x >> 5);
    int b    = wg / WPB;
    int w    = wg % WPB;
    if (b >= B) return;
    int lane = threadIdx.x & 31;

    int rpw = (N + WPB - 1) / WPB;       // 136
    int n0  = w * rpw;
    int n1  = min(N, n0 + rpw);

    const float4* rb = reinterpret_cast<const float4*>(g_r + b * HID);
    float4 rr[5], acc[5];
    #pragma unroll
    for (int k = 0; k < 5; k++) {
        rr[k]  = rb[lane + 32 * k];
        acc[k] = make_float4(0.f, 0.f, 0.f, 0.f);
    }

    float m = -1e30f, s = 0.f;
    const float4* base = reinterpret_cast<const float4*>(gh) + (size_t)b * N * (HID / 4);

    int n = n0;
    if ((n1 - n0) & 1) {                 // odd head: single row
        const float4* p = base + (size_t)n * (HID / 4);
        float4 hv[5];
        #pragma unroll
        for (int k = 0; k < 5; k++) hv[k] = __ldcs(p + lane + 32 * k);
        float d = 0.f;
        #pragma unroll
        for (int k = 0; k < 5; k++)
            d += hv[k].x * rr[k].x + hv[k].y * rr[k].y
               + hv[k].z * rr[k].z + hv[k].w * rr[k].w;
        #pragma unroll
        for (int o = 16; o > 0; o >>= 1) d += __shfl_xor_sync(0xffffffffu, d, o);
        m = d; s = 1.f;
        #pragma unroll
        for (int k = 0; k < 5; k++) acc[k] = hv[k];
        n++;
    }

    for (; n < n1; n += 2) {
        const float4* p0 = base + (size_t)n * (HID / 4);
        const float4* p1 = p0 + (HID / 4);
        float4 h0[5], h1[5];
        #pragma unroll
        for (int k = 0; k < 5; k++) h0[k] = __ldcs(p0 + lane + 32 * k);
        #pragma unroll
        for (int k = 0; k < 5; k++) h1[k] = __ldcs(p1 + lane + 32 * k);

        float d0 = 0.f, d1 = 0.f;
        #pragma unroll
        for (int k = 0; k < 5; k++) {
            d0 += h0[k].x * rr[k].x + h0[k].y * rr[k].y
                + h0[k].z * rr[k].z + h0[k].w * rr[k].w;
            d1 += h1[k].x * rr[k].x + h1[k].y * rr[k].y
                + h1[k].z * rr[k].z + h1[k].w * rr[k].w;
        }
        #pragma unroll
        for (int o = 16; o > 0; o >>= 1) {
            d0 += __shfl_xor_sync(0xffffffffu, d0, o);
            d1 += __shfl_xor_sync(0xffffffffu, d1, o);
        }

        float mn = fmaxf(d0, d1);
        if (mn > m) {                     // warp-uniform
            float c = __expf(m - mn);
            s *= c;
            #pragma unroll
            for (int k = 0; k < 5; k++) {
                acc[k].x *= c; acc[k].y *= c; acc[k].z *= c; acc[k].w *= c;
            }
            m = mn;
        }
        float w0 = __expf(d0 - m);
        float w1 = __expf(d1 - m);
        s += w0 + w1;
        #pragma unroll
        for (int k = 0; k < 5; k++) {
            acc[k].x += w0 * h0[k].x + w1 * h1[k].x;
            acc[k].y += w0 * h0[k].y + w1 * h1[k].y;
            acc[k].z += w0 * h0[k].z + w1 * h1[k].z;
            acc[k].w += w0 * h0[k].w + w1 * h1[k].w;
        }
    }

    float4* pa = reinterpret_cast<float4*>(g_pacc + (size_t)(b * WPB + w) * HID);
    #pragma unroll
    for (int k = 0; k < 5; k++) pa[lane + 32 * k] = acc[k];
    if (lane == 0) { g_pm[b * WPB + w] = m; g_ps[b * WPB + w] = s; }
}

// ---------------------------------------------------------------------------
// Kernel 3: pooled[b,h] = invS * sum_i wsm[i] * pacc[b,i,h]  — FLOAT4 loads.
// grid (B,5) x 256: 32 h-quads (128 h) per block; 8 depth-groups per quad,
// each group sums 19 partials with 16B loads (4x in-flight bytes/slot).
// ---------------------------------------------------------------------------
__global__ void __launch_bounds__(256) k_pooled(int dummy) {
    int b = blockIdx.x;
    int t = threadIdx.x;
    int lane = t & 31, wid = t >> 5;

    __shared__ float wsm[WPB];
    __shared__ float sred[8];
    __shared__ float sInvS;

    float pm = (t < WPB) ? g_pm[b * WPB + t] : -1e30f;
    float ps = (t < WPB) ? g_ps[b * WPB + t] : 0.f;

    float mv = pm;
    #pragma unroll
    for (int o = 16; o > 0; o >>= 1)
        mv = fmaxf(mv, __shfl_xor_sync(0xffffffffu, mv, o));
    if (lane == 0) sred[wid] = mv;
    __syncthreads();
    float M = sred[0];
    #pragma unroll
    for (int i = 1; i < 8; i++) M = fmaxf(M, sred[i]);
    __syncthreads();

    float w = (t < WPB) ? __expf(pm - M) : 0.f;
    if (t < WPB) wsm[t] = w;
    float sv = w * ps;
    #pragma unroll
    for (int o = 16; o > 0; o >>= 1) sv += __shfl_xor_sync(0xffffffffu, sv, o);
    if (lane == 0) sred[wid] = sv;
    __syncthreads();
    if (t == 0) {
        float S = 0.f;
        #pragma unroll
        for (int i = 0; i < 8; i++) S += sred[i];
        sInvS = 1.f / S;
    }
    __syncthreads();

    // quad index within batch: 32 per block; depth group 0..7, 19 partials
    int quad = blockIdx.y * 32 + (t & 31);           // h-quad (4 floats)
    int grp  = t >> 5;                               // 0..7
    const float4* pa = reinterpret_cast<const float4*>(g_pacc + (size_t)b * WPB * HID) + quad;

    float4 a = make_float4(0.f, 0.f, 0.f, 0.f);
    int i0 = grp * 19;
    int i1 = min(i0 + 19, WPB);
    #pragma unroll
    for (int i = i0; i < i0 + 19; i++) {
        if (i < i1) {
            float wi = wsm[i];
            float4 v = pa[(size_t)i * (HID / 4)];
            a.x += wi * v.x; a.y += wi * v.y; a.z += wi * v.z; a.w += wi * v.w;
        }
    }

    __shared__ float4 red[256];
    red[t] = a;
    __syncthreads();
    if (grp == 0) {
        #pragma unroll
        for (int i = 1; i < 8; i++) {
            float4 v = red[t + 32 * i];
            a.x += v.x; a.y += v.y; a.z += v.z; a.w += v.w;
        }
        float iS = sInvS;
        a.x *= iS; a.y *= iS; a.z *= iS; a.w *= iS;
        reinterpret_cast<float4*>(g_pooled + b * HID)[quad] = a;
    }
}

// ---------------------------------------------------------------------------
// Kernel 4: y[b,v] = dot(Wv[v,:], pooled[b,:]) — float4 loads.
// one warp per (b,v); v-major so 16 warps share each Wv row.
// ---------------------------------------------------------------------------
__global__ void __launch_bounds__(256) k_y(const float* __restrict__ Wv) {
    int gw   = blockIdx.x * 8 + (threadIdx.x >> 5);
    int lane = threadIdx.x & 31;
    int v = gw >> 4;
    int b = gw & 15;

    const float4* wr = reinterpret_cast<const float4*>(Wv + (size_t)v * HID);
    const float4* pr = reinterpret_cast<const float4*>(g_pooled + (size_t)b * HID);
    float s = 0.f;
    #pragma unroll
    for (int k = 0; k < 5; k++) {
        float4 a = wr[lane + 32 * k];
        float4 p = pr[lane + 32 * k];
        s += a.x * p.x + a.y * p.y + a.z * p.z + a.w * p.w;
    }
    #pragma unroll
    for (int o = 16; o > 0; o >>= 1) s += __shfl_xor_sync(0xffffffffu, s, o);
    if (lane == 0) g_y[b * HID + v] = s;
}

// ---------------------------------------------------------------------------
// Kernel 5: LayerNorm over 640. grid=B, block=640.
// ---------------------------------------------------------------------------
__device__ __forceinline__ float block_sum_640(float v, float* sred, int t) {
    int lane = t & 31, wid = t >> 5;
    #pragma unroll
    for (int o = 16; o > 0; o >>= 1) v += __shfl_xor_sync(0xffffffffu, v, o);
    if (lane == 0) sred[wid] = v;
    __syncthreads();
    if (wid == 0) {
        float x = (lane < 20) ? sred[lane] : 0.f;
        #pragma unroll
        for (int o = 16; o > 0; o >>= 1) x += __shfl_xor_sync(0xffffffffu, x, o);
        if (lane == 0) sred[0] = x;
    }
    __syncthreads();
    float r = sred[0];
    __syncthreads();
    return r;
}

__global__ void __launch_bounds__(640) k_ln(const float* __restrict__ gamma,
                                            const float* __restrict__ beta,
                                            float* __restrict__ out) {
    int b = blockIdx.x;
    int t = threadIdx.x;
    __shared__ float sred[32];

    float x = g_y[b * HID + t];
    float mean = block_sum_640(x, sred, t) * (1.f / HID);
    float dx = x - mean;
    float var = block_sum_640(dx * dx, sred, t) * (1.f / HID);
    out[b * HID + t] = dx * rsqrtf(var + 1e-5f) * gamma[t] + beta[t];
}

// ---------------------------------------------------------------------------
extern "C" void kernel_launch(void* const* d_in, const int* in_sizes, int n_in,
                              void* d_out, int out_size) {
    const float* gh    = (const float*)d_in[0];
    const float* pos   = (const float*)d_in[1];
    const float* Wq    = (const float*)d_in[2];
    const float* Wk    = (const float*)d_in[3];
    const float* Wv    = (const float*)d_in[4];
    const float* gamma = (const float*)d_in[5];
    const float* beta  = (const float*)d_in[6];
    float* out = (float*)d_out;

    int B = in_sizes[1] / HID;             // 16
    int N = in_sizes[0] / (B * HID);       // 20000
    float scale = 1.0f / sqrtf((float)ADIM);

    k_q<<<(B * ADIM) / 8, 256>>>(pos, Wq);            // 256 blocks
    k_r<<<dim3(B, 5), 512>>>(Wk, scale);              // 80 blocks

    int blocks = (B * WPB) / 8;            // 296 blocks = 2/SM
    k_pass1<<<blocks, 256>>>(gh, B, N);

    k_pooled<<<dim3(B, 5), 256>>>(0);                 // 80 blocks
    k_y<<<(B * HID) / 8, 256>>>(Wv);                  // 1280 blocks
    k_ln<<<B, HID>>>(gamma, beta, out);
}

// round 15
// speedup vs baseline: 1.0471x; 1.0101x over previous
#include <cuda_runtime.h>
#include <cstdint>
#include <cmath>

#define HID  640
#define ADIM 128
#define WPB  148     // warp-partials per batch -> 2368 warps = 296 blocks = 2/SM
#define MAXB 16

// ---- device scratch (no allocations allowed) ----
__device__ float g_q[MAXB * ADIM];
__device__ float g_r[MAXB * HID];
__device__ float g_pacc[(size_t)MAXB * WPB * HID];  // 6 MB
__device__ float g_pm[MAXB * WPB];
__device__ float g_ps[MAXB * WPB];
__device__ float g_pooled[MAXB * HID];
__device__ float g_y[MAXB * HID];

// ---------------------------------------------------------------------------
// Kernel 1a: q[b,a] = dot(Wq[a,:], pos[b,:])   — one warp per output
// ---------------------------------------------------------------------------
__global__ void __launch_bounds__(256) k_q(const float* __restrict__ pos,
                                           const float* __restrict__ Wq) {
    int gw   = blockIdx.x * 8 + (threadIdx.x >> 5);
    int lane = threadIdx.x & 31;
    int b = gw >> 7;
    int a = gw & 127;

    const float* wr = Wq + (size_t)a * HID;
    const float* pr = pos + (size_t)b * HID;
    float s = 0.f;
    #pragma unroll
    for (int k = 0; k < HID / 32; k++) {
        int h = lane + 32 * k;
        s += wr[h] * pr[h];
    }
    #pragma unroll
    for (int o = 16; o > 0; o >>= 1) s += __shfl_xor_sync(0xffffffffu, s, o);
    if (lane == 0) g_q[b * ADIM + a] = s;
}

// ---------------------------------------------------------------------------
// Kernel 1b: r[b,h] = scale * sum_a Wk[a,h] * q[b,a]
// grid (B,5) x 512: 128 h per block, 4 threads per h (32 a's each)
// ---------------------------------------------------------------------------
__global__ void __launch_bounds__(512) k_r(const float* __restrict__ Wk,
                                           float scale) {
    int b = blockIdx.x;
    int t = threadIdx.x;
    int h = blockIdx.y * 128 + (t & 127);
    int q = t >> 7;

    __shared__ float qs[ADIM];
    if (t < ADIM) qs[t] = g_q[b * ADIM + t];
    __syncthreads();

    float s = 0.f;
    int a0 = q * 32;
    #pragma unroll
    for (int a = 0; a < 32; a++)
        s += Wk[(size_t)(a0 + a) * HID + h] * qs[a0 + a];

    __shared__ float red[512];
    red[t] = s;
    __syncthreads();
    if (q == 0)
        g_r[b * HID + h] = (s + red[t + 128] + red[t + 256] + red[t + 384]) * scale;
}

// ---------------------------------------------------------------------------
// Kernel 2: streaming pass over gene_hiddens (819 MB), 2-ROW LDG pipeline
// (R8/R11-proven ~118us = 6.9 TB/s = measured roofline for this pattern).
// ---------------------------------------------------------------------------
__global__ void __launch_bounds__(256, 2) k_pass1(const float* __restrict__ gh,
                                                  int B, int N) {
    int wg   = blockIdx.x * 8 + (threadIdx.x >> 5);
    int b    = wg / WPB;
    int w    = wg % WPB;
    if (b >= B) return;
    int lane = threadIdx.x & 31;

    int rpw = (N + WPB - 1) / WPB;       // 136
    int n0  = w * rpw;
    int n1  = min(N, n0 + rpw);

    const float4* rb = reinterpret_cast<const float4*>(g_r + b * HID);
    float4 rr[5], acc[5];
    #pragma unroll
    for (int k = 0; k < 5; k++) {
        rr[k]  = rb[lane + 32 * k];
        acc[k] = make_float4(0.f, 0.f, 0.f, 0.f);
    }

    float m = -1e30f, s = 0.f;
    const float4* base = reinterpret_cast<const float4*>(gh) + (size_t)b * N * (HID / 4);

    int n = n0;
    if ((n1 - n0) & 1) {                 // odd head: single row
        const float4* p = base + (size_t)n * (HID / 4);
        float4 hv[5];
        #pragma unroll
        for (int k = 0; k < 5; k++) hv[k] = __ldcs(p + lane + 32 * k);
        float d = 0.f;
        #pragma unroll
        for (int k = 0; k < 5; k++)
            d += hv[k].x * rr[k].x + hv[k].y * rr[k].y
               + hv[k].z * rr[k].z + hv[k].w * rr[k].w;
        #pragma unroll
        for (int o = 16; o > 0; o >>= 1) d += __shfl_xor_sync(0xffffffffu, d, o);
        m = d; s = 1.f;
        #pragma unroll
        for (int k = 0; k < 5; k++) acc[k] = hv[k];
        n++;
    }

    for (; n < n1; n += 2) {
        const float4* p0 = base + (size_t)n * (HID / 4);
        const float4* p1 = p0 + (HID / 4);
        float4 h0[5], h1[5];
        #pragma unroll
        for (int k = 0; k < 5; k++) h0[k] = __ldcs(p0 + lane + 32 * k);
        #pragma unroll
        for (int k = 0; k < 5; k++) h1[k] = __ldcs(p1 + lane + 32 * k);

        float d0 = 0.f, d1 = 0.f;
        #pragma unroll
        for (int k = 0; k < 5; k++) {
            d0 += h0[k].x * rr[k].x + h0[k].y * rr[k].y
                + h0[k].z * rr[k].z + h0[k].w * rr[k].w;
            d1 += h1[k].x * rr[k].x + h1[k].y * rr[k].y
                + h1[k].z * rr[k].z + h1[k].w * rr[k].w;
        }
        #pragma unroll
        for (int o = 16; o > 0; o >>= 1) {
            d0 += __shfl_xor_sync(0xffffffffu, d0, o);
            d1 += __shfl_xor_sync(0xffffffffu, d1, o);
        }

        float mn = fmaxf(d0, d1);
        if (mn > m) {                     // warp-uniform
            float c = __expf(m - mn);
            s *= c;
            #pragma unroll
            for (int k = 0; k < 5; k++) {
                acc[k].x *= c; acc[k].y *= c; acc[k].z *= c; acc[k].w *= c;
            }
            m = mn;
        }
        float w0 = __expf(d0 - m);
        float w1 = __expf(d1 - m);
        s += w0 + w1;
        #pragma unroll
        for (int k = 0; k < 5; k++) {
            acc[k].x += w0 * h0[k].x + w1 * h1[k].x;
            acc[k].y += w0 * h0[k].y + w1 * h1[k].y;
            acc[k].z += w0 * h0[k].z + w1 * h1[k].z;
            acc[k].w += w0 * h0[k].w + w1 * h1[k].w;
        }
    }

    float4* pa = reinterpret_cast<float4*>(g_pacc + (size_t)(b * WPB + w) * HID);
    #pragma unroll
    for (int k = 0; k < 5; k++) pa[lane + 32 * k] = acc[k];
    if (lane == 0) { g_pm[b * WPB + w] = m; g_ps[b * WPB + w] = s; }
}

// ---------------------------------------------------------------------------
// Kernel 3: pooled[b,h] = invS * sum_i wsm[i] * pacc[b,i,h]
// R13-proven config: grid (B,10) x 256 — 64 h per block, 4 threads per h,
// 37 partials each (deep per-thread load chains; scalar coalesced loads).
// ---------------------------------------------------------------------------
__global__ void __launch_bounds__(256) k_pooled(int dummy) {
    int b = blockIdx.x;
    int t = threadIdx.x;
    int lane = t & 31, wid = t >> 5;

    __shared__ float wsm[WPB];
    __shared__ float sred[8];
    __shared__ float sInvS;

    float pm = (t < WPB) ? g_pm[b * WPB + t] : -1e30f;
    float ps = (t < WPB) ? g_ps[b * WPB + t] : 0.f;

    float mv = pm;
    #pragma unroll
    for (int o = 16; o > 0; o >>= 1)
        mv = fmaxf(mv, __shfl_xor_sync(0xffffffffu, mv, o));
    if (lane == 0) sred[wid] = mv;
    __syncthreads();
    float M = sred[0];
    #pragma unroll
    for (int i = 1; i < 8; i++) M = fmaxf(M, sred[i]);
    __syncthreads();

    float w = (t < WPB) ? __expf(pm - M) : 0.f;
    if (t < WPB) wsm[t] = w;
    float sv = w * ps;
    #pragma unroll
    for (int o = 16; o > 0; o >>= 1) sv += __shfl_xor_sync(0xffffffffu, sv, o);
    if (lane == 0) sred[wid] = sv;
    __syncthreads();
    if (t == 0) {
        float S = 0.f;
        #pragma unroll
        for (int i = 0; i < 8; i++) S += sred[i];
        sInvS = 1.f / S;
    }
    __syncthreads();

    // 4 threads per h, 37 partials each
    int h = blockIdx.y * 64 + (t & 63);
    int q = t >> 6;
    const float* pa = g_pacc + (size_t)b * WPB * HID + h;

    float a = 0.f;
    int i0 = q * 37;
    #pragma unroll
    for (int i = i0; i < i0 + 37; i++)
        a += wsm[i] * pa[(size_t)i * HID];

    __shared__ float red[256];
    red[t] = a;
    __syncthreads();
    if (q == 0)
        g_pooled[b * HID + h] =
            (a + red[t + 64] + red[t + 128] + red[t + 192]) * sInvS;
}

// ---------------------------------------------------------------------------
// Kernel 4: y[b,v] = dot(Wv[v,:], pooled[b,:]) — float4 loads.
// one warp per (b,v); v-major so 16 warps share each Wv row.
// ---------------------------------------------------------------------------
__global__ void __launch_bounds__(256) k_y(const float* __restrict__ Wv) {
    int gw   = blockIdx.x * 8 + (threadIdx.x >> 5);
    int lane = threadIdx.x & 31;
    int v = gw >> 4;
    int b = gw & 15;

    const float4* wr = reinterpret_cast<const float4*>(Wv + (size_t)v * HID);
    const float4* pr = reinterpret_cast<const float4*>(g_pooled + (size_t)b * HID);
    float s = 0.f;
    #pragma unroll
    for (int k = 0; k < 5; k++) {
        float4 a = wr[lane + 32 * k];
        float4 p = pr[lane + 32 * k];
        s += a.x * p.x + a.y * p.y + a.z * p.z + a.w * p.w;
    }
    #pragma unroll
    for (int o = 16; o > 0; o >>= 1) s += __shfl_xor_sync(0xffffffffu, s, o);
    if (lane == 0) g_y[b * HID + v] = s;
}

// ---------------------------------------------------------------------------
// Kernel 5: LayerNorm over 640. grid=B, block=640.
// ---------------------------------------------------------------------------
__device__ __forceinline__ float block_sum_640(float v, float* sred, int t) {
    int lane = t & 31, wid = t >> 5;
    #pragma unroll
    for (int o = 16; o > 0; o >>= 1) v += __shfl_xor_sync(0xffffffffu, v, o);
    if (lane == 0) sred[wid] = v;
    __syncthreads();
    if (wid == 0) {
        float x = (lane < 20) ? sred[lane] : 0.f;
        #pragma unroll
        for (int o = 16; o > 0; o >>= 1) x += __shfl_xor_sync(0xffffffffu, x, o);
        if (lane == 0) sred[0] = x;
    }
    __syncthreads();
    float r = sred[0];
    __syncthreads();
    return r;
}

__global__ void __launch_bounds__(640) k_ln(const float* __restrict__ gamma,
                                            const float* __restrict__ beta,
                                            float* __restrict__ out) {
    int b = blockIdx.x;
    int t = threadIdx.x;
    __shared__ float sred[32];

    float x = g_y[b * HID + t];
    float mean = block_sum_640(x, sred, t) * (1.f / HID);
    float dx = x - mean;
    float var = block_sum_640(dx * dx, sred, t) * (1.f / HID);
    out[b * HID + t] = dx * rsqrtf(var + 1e-5f) * gamma[t] + beta[t];
}

// ---------------------------------------------------------------------------
extern "C" void kernel_launch(void* const* d_in, const int* in_sizes, int n_in,
                              void* d_out, int out_size) {
    const float* gh    = (const float*)d_in[0];
    const float* pos   = (const float*)d_in[1];
    const float* Wq    = (const float*)d_in[2];
    const float* Wk    = (const float*)d_in[3];
    const float* Wv    = (const float*)d_in[4];
    const float* gamma = (const float*)d_in[5];
    const float* beta  = (const float*)d_in[6];
    float* out = (float*)d_out;

    int B = in_sizes[1] / HID;             // 16
    int N = in_sizes[0] / (B * HID);       // 20000
    float scale = 1.0f / sqrtf((float)ADIM);

    k_q<<<(B * ADIM) / 8, 256>>>(pos, Wq);            // 256 blocks
    k_r<<<dim3(B, 5), 512>>>(Wk, scale);              // 80 blocks

    int blocks = (B * WPB) / 8;            // 296 blocks = 2/SM
    k_pass1<<<blocks, 256>>>(gh, B, N);

    k_pooled<<<dim3(B, 10), 256>>>(0);                // 160 blocks
    k_y<<<(B * HID) / 8, 256>>>(Wv);                  // 1280 blocks
    k_ln<<<B, HID>>>(gamma, beta, out);
}